// round 13
// baseline (speedup 1.0000x reference)
#include <cuda_runtime.h>
#include <cuda_fp16.h>
#include <math.h>
#include <stdint.h>

#define DNUM   4
#define N_MAX  262144
#define FDIM   100
#define HDIM   128
#define TILE_M 256          // points per CTA (4 wgs x 64)
#define NT     512
#define TWO_PI_F 6.2831853071795864769f

// ---------------- device scratch (allocation-free) ----------------
__device__ int g_counts[DNUM];
__device__ int g_idx[DNUM * N_MAX];
// f16 weights, transposed [n][k], XOR-swizzled images, 32KB each.
__device__ __align__(16) uint8_t g_w1_hi[DNUM][2][32768];
__device__ __align__(16) uint8_t g_w2_hi[DNUM][32768];
__device__ __align__(16) uint8_t g_w3_hi[DNUM][32768];

// swizzled byte offset inside a [rows][128 cols-f16] image (256B rows)
__device__ __host__ __forceinline__ int sw_off(int row, int col) {
    return row * 256 + ((((col >> 3) ^ (row & 7)) << 4)) + ((col & 7) << 1);
}

// ---------------- prep kernels ----------------
__global__ void zero_counts_kernel() {
    if (threadIdx.x < DNUM) g_counts[threadIdx.x] = 0;
}
__global__ void bucket_kernel(const float* __restrict__ x, int n) {
    int i = blockIdx.x * blockDim.x + threadIdx.x;
    if (i >= n) return;
    float xv = x[i];
    int d = (xv < -0.5f) ? 0 : (xv < 0.0f) ? 1 : (xv < 0.5f) ? 2 : 3;
    int pos = atomicAdd(&g_counts[d], 1);
    g_idx[d * N_MAX + pos] = i;
}

// W1 col j (0..255): f=j>>1, s=j&1 -> W1 row f+100s (f>=100 pad 0). W2/W3 direct.
__global__ void prep_weights_kernel(const float* __restrict__ W1,
                                    const float* __restrict__ W2,
                                    const float* __restrict__ W3) {
    const int T1 = DNUM * 2 * HDIM * HDIM;
    const int T2 = DNUM * HDIM * HDIM;
    int idx = blockIdx.x * blockDim.x + threadIdx.x;
    float w; uint8_t* hiA; int off;
    if (idx < T1) {
        int d = idx / (2 * HDIM * HDIM), r = idx % (2 * HDIM * HDIM);
        int c = r / (HDIM * HDIM), r2 = r % (HDIM * HDIM);
        int k = r2 / HDIM, n = r2 % HDIM;
        int j = c * 128 + k, f = j >> 1, s = j & 1;
        w = (f < FDIM) ? W1[((size_t)d * 2 * FDIM + (f + FDIM * s)) * HDIM + n] : 0.0f;
        off = sw_off(n, k); hiA = g_w1_hi[d][c];
    } else if (idx < T1 + T2) {
        int r0 = idx - T1;
        int d = r0 / (HDIM * HDIM), r2 = r0 % (HDIM * HDIM);
        int k = r2 / HDIM, n = r2 % HDIM;
        w = W2[((size_t)d * HDIM + k) * HDIM + n];
        off = sw_off(n, k); hiA = g_w2_hi[d];
    } else if (idx < T1 + 2 * T2) {
        int r0 = idx - T1 - T2;
        int d = r0 / (HDIM * HDIM), r2 = r0 % (HDIM * HDIM);
        int k = r2 / HDIM, n = r2 % HDIM;
        w = W3[((size_t)d * HDIM + k) * HDIM + n];
        off = sw_off(n, k); hiA = g_w3_hi[d];
    } else return;
    *(__half*)(hiA + off) = __float2half_rn(w);
}

// ---------------- asm helpers ----------------
__device__ __forceinline__ uint32_t smem_u32(const void* p) {
    uint32_t a;
    asm("{ .reg .u64 t; cvta.to.shared.u64 t, %1; cvt.u32.u64 %0, t; }" : "=r"(a) : "l"(p));
    return a;
}
__device__ __forceinline__ void ldsm_x4(uint32_t* r, uint32_t addr) {
    asm volatile("ldmatrix.sync.aligned.m8n8.x4.shared.b16 {%0,%1,%2,%3}, [%4];"
        : "=r"(r[0]), "=r"(r[1]), "=r"(r[2]), "=r"(r[3]) : "r"(addr));
}
__device__ __forceinline__ void mma16816(float* d, const uint32_t* a, uint32_t b0, uint32_t b1) {
    asm volatile("mma.sync.aligned.m16n8k16.row.col.f32.f16.f16.f32 "
        "{%0,%1,%2,%3}, {%4,%5,%6,%7}, {%8,%9}, {%0,%1,%2,%3};"
        : "+f"(d[0]), "+f"(d[1]), "+f"(d[2]), "+f"(d[3])
        : "r"(a[0]), "r"(a[1]), "r"(a[2]), "r"(a[3]), "r"(b0), "r"(b1));
}
#define CP_COMMIT() asm volatile("cp.async.commit_group;" ::: "memory")
#define CP_WAIT(n)  asm volatile("cp.async.wait_group %0;" :: "n"(n) : "memory")
#define WGBAR(id)   asm volatile("bar.sync %0, 128;" :: "r"(id) : "memory")
__device__ __forceinline__ void cp_issue32k(uint32_t smem_dst, const uint8_t* gsrc, int tid) {
#pragma unroll
    for (int i = 0; i < 4; i++) {
        int off = (tid + i * NT) * 16;
        asm volatile("cp.async.cg.shared.global [%0], [%1], 16;"
            :: "r"(smem_dst + off), "l"(gsrc + off) : "memory");
    }
}

// ---------------- SMEM layout (bytes) ----------------
#define S_A      0          // 4 wg A-images, 64x128 f16 swizzled, 16KB each
#define S_W1C0   65536
#define S_W1C1   98304
#define S_W2     131072
#define S_W3     163840
#define S_MISC   196608
#define MS_BX    0          // 128 f32
#define MS_BT    512
#define MS_B1    1024
#define MS_B2    1536
#define MS_B3    2048
#define MS_W4    2560
#define MS_X     3072       // 256 f32
#define MS_T     4096
#define MS_IDX   5120       // 256 int
#define MS_PART  6144       // 16 x 64 f32 = 4KB
#define SMEM_TOTAL (S_MISC + 6144 + 4096)

__device__ __forceinline__ float silu_f(float v) { return v / (1.0f + __expf(-v)); }
__device__ __forceinline__ uint32_t pack2(float a, float b) {
    __half2 h = __halves2half2(__float2half_rn(a), __float2half_rn(b));
    return *(uint32_t*)&h;
}

// One K=128 MMA pass over a 64-row wg image: acc += A * W.  Warp tile: 64(M) x 32(N).
__device__ __forceinline__ void mma_pass(float acc[4][4][4], uint32_t aImg,
                                         uint32_t wImg, int n0, int lane) {
    const int rowl = ((lane >> 3) & 1) * 8 + (lane & 7);
    const int k8   = (lane >> 4) & 1;
    const int l7   = lane & 7;
    uint32_t aBase[4], bBase[2];
#pragma unroll
    for (int s = 0; s < 4; s++)
        aBase[s] = aImg + (uint32_t)(s * 16 + rowl) * 256;
#pragma unroll
    for (int v = 0; v < 2; v++)
        bBase[v] = wImg + (uint32_t)(n0 + v * 16 + rowl) * 256;
#pragma unroll
    for (int ks = 0; ks < 8; ks++) {
        const uint32_t swz = (uint32_t)(((ks * 2 + k8) ^ l7) << 4);
        uint32_t aH[4][4], bH[2][4];
#pragma unroll
        for (int s = 0; s < 4; s++) ldsm_x4(aH[s], aBase[s] + swz);
#pragma unroll
        for (int v = 0; v < 2; v++) ldsm_x4(bH[v], bBase[v] + swz);
#pragma unroll
        for (int v = 0; v < 2; v++)
#pragma unroll
            for (int h = 0; h < 2; h++) {
                const int u = v * 2 + h;
#pragma unroll
                for (int s = 0; s < 4; s++)
                    mma16816(acc[s][u], aH[s], bH[v][h], bH[v][h + 2]);
            }
    }
}

// bias+SiLU, round to f16, store in place into wg A-image; zero acc
__device__ __forceinline__ void epilogue(float acc[4][4][4], char* smem, uint32_t aOff,
                                         const float* bias, int n0, int lane) {
    const int lr = lane >> 2, lc = (lane & 3) * 2;
#pragma unroll
    for (int s = 0; s < 4; s++)
#pragma unroll
        for (int u = 0; u < 4; u++) {
            int n_ = n0 + u * 8 + lc;
            float b0 = bias[n_], b1v = bias[n_ + 1];
            float v0 = silu_f(acc[s][u][0] + b0);
            float v1 = silu_f(acc[s][u][1] + b1v);
            float v2 = silu_f(acc[s][u][2] + b0);
            float v3 = silu_f(acc[s][u][3] + b1v);
            acc[s][u][0] = acc[s][u][1] = acc[s][u][2] = acc[s][u][3] = 0.0f;
            int mA = s * 16 + lr;
            int chunk = (n_ >> 3) ^ (lr & 7);
            uint32_t addrA = aOff + (uint32_t)mA * 256 + (chunk << 4) + lc * 2;
            *(uint32_t*)(smem + addrA) = pack2(v0, v1);
            uint32_t addrB = aOff + (uint32_t)(mA + 8) * 256 + (chunk << 4) + lc * 2;
            *(uint32_t*)(smem + addrB) = pack2(v2, v3);
        }
}

// Fourier features for one K=128 chunk into wg A-image; 128 threads, 64 points
__device__ __forceinline__ void gen_feats(char* smem, uint32_t aOff,
                                          const float* sBx, const float* sBt,
                                          float xv, float tv,
                                          int chunk, int wg_tid) {
    const int m = wg_tid >> 1, q = wg_tid & 1;
    const int fbase = chunk * 64 + q * 32;
#pragma unroll
    for (int g = 0; g < 8; g++) {
        uint32_t hi4[4];
#pragma unroll
        for (int i = 0; i < 4; i++) {
            int f = fbase + g * 4 + i;
            float s = 0.0f, c = 0.0f;
            if (f < FDIM) {
                float pr = TWO_PI_F * (xv * sBx[f] + tv * sBt[f]);
                __sincosf(pr, &s, &c);
            }
            hi4[i] = pack2(s, c);
        }
        int c0 = q * 64 + g * 8;
        uint32_t addr = aOff + (uint32_t)m * 256 + ((((c0 >> 3) ^ (m & 7)) << 4));
        *(uint4*)(smem + addr) = make_uint4(hi4[0], hi4[1], hi4[2], hi4[3]);
    }
}

__global__ void __launch_bounds__(NT, 1) xpinn_mma_kernel(
    const float* __restrict__ x, const float* __restrict__ t,
    const float* __restrict__ Bf,
    const float* __restrict__ b1, const float* __restrict__ b2,
    const float* __restrict__ b3,
    const float* __restrict__ W4, const float* __restrict__ b4,
    float* __restrict__ out) {
    const int dom = blockIdx.y;
    const int base_pt = blockIdx.x * TILE_M;
    const int cnt = g_counts[dom];
    if (base_pt >= cnt) return;

    extern __shared__ __align__(16) char smem[];
    const uint32_t sb = smem_u32(smem);
    const int tid = threadIdx.x;
    const int wid = tid >> 5, lane = tid & 31;
    const int wg = wid >> 2;            // 0..3: independent workgroup
    const int wn = wid & 3;             // warp-in-wg: owns n0 = wn*32
    const int n0 = wn * 32;
    const int wg_tid = tid & 127;
    const int bar_id = 1 + wg;
    const uint32_t aOff = S_A + (uint32_t)wg * 16384;
    const uint32_t aImg = sb + aOff;
    const int nm = (cnt - base_pt < TILE_M) ? (cnt - base_pt) : TILE_M;

    float* sBx = (float*)(smem + S_MISC + MS_BX);
    float* sBt = (float*)(smem + S_MISC + MS_BT);
    float* sB1 = (float*)(smem + S_MISC + MS_B1);
    float* sB2 = (float*)(smem + S_MISC + MS_B2);
    float* sB3 = (float*)(smem + S_MISC + MS_B3);
    float* sW4 = (float*)(smem + S_MISC + MS_W4);
    float* sX  = (float*)(smem + S_MISC + MS_X);
    float* sT  = (float*)(smem + S_MISC + MS_T);
    int*   sIdx = (int*)(smem + S_MISC + MS_IDX);
    float* sPart = (float*)(smem + S_MISC + MS_PART);

    // Load ALL weights once (static for CTA lifetime).
    cp_issue32k(sb + S_W1C0, g_w1_hi[dom][0], tid);
    cp_issue32k(sb + S_W1C1, g_w1_hi[dom][1], tid);
    cp_issue32k(sb + S_W2,   g_w2_hi[dom],    tid);
    cp_issue32k(sb + S_W3,   g_w3_hi[dom],    tid);
    CP_COMMIT();

    if (tid < TILE_M) {
        if (tid < nm) {
            int i = g_idx[dom * N_MAX + base_pt + tid];
            sIdx[tid] = i; sX[tid] = x[i]; sT[tid] = t[i];
        } else { sIdx[tid] = -1; sX[tid] = 0.0f; sT[tid] = 0.0f; }
    }
    if (tid < HDIM) {
        sBx[tid] = (tid < FDIM) ? Bf[(dom * FDIM + tid) * 2]     : 0.0f;
        sBt[tid] = (tid < FDIM) ? Bf[(dom * FDIM + tid) * 2 + 1] : 0.0f;
        sB1[tid] = b1[dom * HDIM + tid];
        sB2[tid] = b2[dom * HDIM + tid];
        sB3[tid] = b3[dom * HDIM + tid];
        sW4[tid] = W4[dom * HDIM + tid];
    }
    __syncthreads();

    const float xv = sX[wg * 64 + (wg_tid >> 1)];
    const float tv = sT[wg * 64 + (wg_tid >> 1)];

    float acc[4][4][4];
#pragma unroll
    for (int s = 0; s < 4; s++)
#pragma unroll
        for (int u = 0; u < 4; u++)
#pragma unroll
            for (int r = 0; r < 4; r++) acc[s][u][r] = 0.0f;

    // ---- layer 1, K chunk 0 ----
    gen_feats(smem, aOff, sBx, sBt, xv, tv, 0, wg_tid);
    CP_WAIT(0);
    __syncthreads();   // weights + feats0 visible; LAST full-CTA sync
    mma_pass(acc, aImg, sb + S_W1C0, n0, lane);
    WGBAR(bar_id);
    // ---- layer 1, K chunk 1 (A image reused) ----
    gen_feats(smem, aOff, sBx, sBt, xv, tv, 1, wg_tid);
    WGBAR(bar_id);
    mma_pass(acc, aImg, sb + S_W1C1, n0, lane);
    WGBAR(bar_id);
    // ---- layer 2 ----
    epilogue(acc, smem, aOff, sB1, n0, lane);
    WGBAR(bar_id);
    mma_pass(acc, aImg, sb + S_W2, n0, lane);
    WGBAR(bar_id);
    // ---- layer 3 ----
    epilogue(acc, smem, aOff, sB2, n0, lane);
    WGBAR(bar_id);
    mma_pass(acc, aImg, sb + S_W3, n0, lane);

    // ---- head: p = sum_n silu(z3 + b3[n]) * W4[n] ----
    {
        const int lr = lane >> 2, lc = (lane & 3) * 2;
        float hp[4][2];
#pragma unroll
        for (int s = 0; s < 4; s++) { hp[s][0] = 0.0f; hp[s][1] = 0.0f; }
#pragma unroll
        for (int s = 0; s < 4; s++)
#pragma unroll
            for (int u = 0; u < 4; u++) {
                int n_ = n0 + u * 8 + lc;
                float w0 = sW4[n_], w1 = sW4[n_ + 1];
                float b0 = sB3[n_], b1v = sB3[n_ + 1];
                hp[s][0] += silu_f(acc[s][u][0] + b0) * w0 + silu_f(acc[s][u][1] + b1v) * w1;
                hp[s][1] += silu_f(acc[s][u][2] + b0) * w0 + silu_f(acc[s][u][3] + b1v) * w1;
            }
#pragma unroll
        for (int off = 1; off <= 2; off <<= 1)
#pragma unroll
            for (int s = 0; s < 4; s++) {
                hp[s][0] += __shfl_xor_sync(0xFFFFFFFF, hp[s][0], off);
                hp[s][1] += __shfl_xor_sync(0xFFFFFFFF, hp[s][1], off);
            }
        if ((lane & 3) == 0)
#pragma unroll
            for (int s = 0; s < 4; s++) {
                sPart[(wg * 4 + wn) * 64 + s * 16 + lr]     = hp[s][0];
                sPart[(wg * 4 + wn) * 64 + s * 16 + lr + 8] = hp[s][1];
            }
    }
    WGBAR(bar_id);
    if (wg_tid < 64) {
        int idx = sIdx[wg * 64 + wg_tid];
        if (idx >= 0) {
            float* p = sPart + wg * 256 + wg_tid;
            out[idx] = p[0] + p[64] + p[128] + p[192] + b4[dom];
        }
    }
}

// ---------------- launch ----------------
extern "C" void kernel_launch(void* const* d_in, const int* in_sizes, int n_in,
                              void* d_out, int out_size) {
    const float* x  = (const float*)d_in[0];
    const float* t  = (const float*)d_in[1];
    const float* Bf = (const float*)d_in[2];
    const float* W1 = (const float*)d_in[3];
    const float* b1 = (const float*)d_in[4];
    const float* W2 = (const float*)d_in[5];
    const float* b2 = (const float*)d_in[6];
    const float* W3 = (const float*)d_in[7];
    const float* b3 = (const float*)d_in[8];
    const float* W4 = (const float*)d_in[9];
    const float* b4 = (const float*)d_in[10];
    float* out = (float*)d_out;
    const int n = in_sizes[0];
    (void)n_in; (void)out_size;

    cudaFuncSetAttribute(xpinn_mma_kernel,
                         cudaFuncAttributeMaxDynamicSharedMemorySize, SMEM_TOTAL);

    zero_counts_kernel<<<1, 32>>>();
    bucket_kernel<<<(n + 255) / 256, 256>>>(x, n);
    {
        const int total = DNUM * 2 * HDIM * HDIM + 2 * DNUM * HDIM * HDIM;
        prep_weights_kernel<<<(total + 255) / 256, 256>>>(W1, W2, W3);
    }
    dim3 grid((n + TILE_M - 1) / TILE_M, DNUM);
    xpinn_mma_kernel<<<grid, NT, SMEM_TOTAL>>>(x, t, Bf, b1, b2, b3, W4, b4, out);
}

// round 14
// speedup vs baseline: 1.4667x; 1.4667x over previous
#include <cuda_runtime.h>
#include <cuda_fp16.h>
#include <math.h>
#include <stdint.h>

#define DNUM   4
#define N_MAX  262144
#define FDIM   100
#define HDIM   128
#define TILE_M 128
#define NT     256
#define TWO_PI_F 6.2831853071795864769f

// ---------------- device scratch (allocation-free) ----------------
__device__ int g_counts[DNUM];
__device__ int g_idx[DNUM * N_MAX];
// f16 weights, transposed [n][k], XOR-swizzled images, 32KB each.
// W1 chunk1 uses only 80 k-cols (freqs 64..99 + pad to 104).
__device__ __align__(16) uint8_t g_w1_hi[DNUM][2][32768];
__device__ __align__(16) uint8_t g_w2_hi[DNUM][32768];
__device__ __align__(16) uint8_t g_w3_hi[DNUM][32768];

// swizzled byte offset inside a [rows][128 cols-f16] image (256B rows)
__device__ __host__ __forceinline__ int sw_off(int row, int col) {
    return row * 256 + ((((col >> 3) ^ (row & 7)) << 4)) + ((col & 7) << 1);
}

// ---------------- prep kernels ----------------
__global__ void zero_counts_kernel() {
    if (threadIdx.x < DNUM) g_counts[threadIdx.x] = 0;
}

// Block-aggregated bucketing: 4 smem counters, one global atomic per domain per block.
__global__ void bucket_kernel(const float* __restrict__ x, int n) {
    __shared__ int s_cnt[DNUM];
    __shared__ int s_base[DNUM];
    const int tid = threadIdx.x;
    if (tid < DNUM) s_cnt[tid] = 0;
    __syncthreads();
    const int i = blockIdx.x * blockDim.x + tid;
    int d = 0, pos = 0;
    if (i < n) {
        float xv = x[i];
        d = (xv < -0.5f) ? 0 : (xv < 0.0f) ? 1 : (xv < 0.5f) ? 2 : 3;
        pos = atomicAdd(&s_cnt[d], 1);
    }
    __syncthreads();
    if (tid < DNUM) s_base[tid] = atomicAdd(&g_counts[tid], s_cnt[tid]);
    __syncthreads();
    if (i < n) g_idx[d * N_MAX + s_base[d] + pos] = i;
}

// W1 col j: f=j>>1, s=j&1 -> W1 row f+100s (f>=100 pad 0).
// chunk0: j = 0..127 (f 0..63). chunk1: j = 128+k, k<80 (f 64..103; real to 99).
__global__ void prep_weights_kernel(const float* __restrict__ W1,
                                    const float* __restrict__ W2,
                                    const float* __restrict__ W3) {
    const int T1 = DNUM * 2 * HDIM * HDIM;
    const int T2 = DNUM * HDIM * HDIM;
    int idx = blockIdx.x * blockDim.x + threadIdx.x;
    float w; uint8_t* hiA; int off;
    if (idx < T1) {
        int d = idx / (2 * HDIM * HDIM), r = idx % (2 * HDIM * HDIM);
        int c = r / (HDIM * HDIM), r2 = r % (HDIM * HDIM);
        int k = r2 / HDIM, n = r2 % HDIM;
        int j = c * 128 + k, f = j >> 1, s = j & 1;
        w = (f < FDIM) ? W1[((size_t)d * 2 * FDIM + (f + FDIM * s)) * HDIM + n] : 0.0f;
        off = sw_off(n, k); hiA = g_w1_hi[d][c];
    } else if (idx < T1 + T2) {
        int r0 = idx - T1;
        int d = r0 / (HDIM * HDIM), r2 = r0 % (HDIM * HDIM);
        int k = r2 / HDIM, n = r2 % HDIM;
        w = W2[((size_t)d * HDIM + k) * HDIM + n];
        off = sw_off(n, k); hiA = g_w2_hi[d];
    } else if (idx < T1 + 2 * T2) {
        int r0 = idx - T1 - T2;
        int d = r0 / (HDIM * HDIM), r2 = r0 % (HDIM * HDIM);
        int k = r2 / HDIM, n = r2 % HDIM;
        w = W3[((size_t)d * HDIM + k) * HDIM + n];
        off = sw_off(n, k); hiA = g_w3_hi[d];
    } else return;
    *(__half*)(hiA + off) = __float2half_rn(w);
}

// ---------------- asm helpers ----------------
__device__ __forceinline__ uint32_t smem_u32(const void* p) {
    uint32_t a;
    asm("{ .reg .u64 t; cvta.to.shared.u64 t, %1; cvt.u32.u64 %0, t; }" : "=r"(a) : "l"(p));
    return a;
}
__device__ __forceinline__ void ldsm_x4(uint32_t* r, uint32_t addr) {
    asm volatile("ldmatrix.sync.aligned.m8n8.x4.shared.b16 {%0,%1,%2,%3}, [%4];"
        : "=r"(r[0]), "=r"(r[1]), "=r"(r[2]), "=r"(r[3]) : "r"(addr));
}
__device__ __forceinline__ void mma16816(float* d, const uint32_t* a, uint32_t b0, uint32_t b1) {
    asm volatile("mma.sync.aligned.m16n8k16.row.col.f32.f16.f16.f32 "
        "{%0,%1,%2,%3}, {%4,%5,%6,%7}, {%8,%9}, {%0,%1,%2,%3};"
        : "+f"(d[0]), "+f"(d[1]), "+f"(d[2]), "+f"(d[3])
        : "r"(a[0]), "r"(a[1]), "r"(a[2]), "r"(a[3]), "r"(b0), "r"(b1));
}
#define CP_COMMIT() asm volatile("cp.async.commit_group;" ::: "memory")
#define CP_WAIT(n)  asm volatile("cp.async.wait_group %0;" :: "n"(n) : "memory")
__device__ __forceinline__ void cp_issue32k(uint32_t smem_dst, const uint8_t* gsrc, int tid) {
#pragma unroll
    for (int i = 0; i < 8; i++) {
        int off = (tid + i * NT) * 16;
        asm volatile("cp.async.cg.shared.global [%0], [%1], 16;"
            :: "r"(smem_dst + off), "l"(gsrc + off) : "memory");
    }
}

// ---------------- SMEM layout (bytes) ----------------
#define S_P      0          // activations, 128x128 f16 swizzled, 32KB
#define S_W0     32768      // weight stage 0, 32KB
#define S_W1     65536      // weight stage 1, 32KB
#define S_MISC   98304
#define MS_BX    0          // 128 f32
#define MS_BT    512
#define MS_B1    1024
#define MS_B2    1536
#define MS_B3    2048
#define MS_W4    2560
#define MS_X     3072
#define MS_T     3584
#define MS_IDX   4096
#define MS_PART  4608       // 4 x 128 f32
#define SMEM_TOTAL (S_MISC + 4608 + 2048)

__device__ __forceinline__ float silu_f(float v) { return v / (1.0f + __expf(-v)); }
__device__ __forceinline__ uint32_t pack2(float a, float b) {
    __half2 h = __halves2half2(__float2half_rn(a), __float2half_rn(b));
    return *(uint32_t*)&h;
}

// One K=16*NKS MMA pass: acc += A(P) * W(stage).  Warp tile: 64(M) x 32(N).
template <int NKS>
__device__ __forceinline__ void mma_pass(float acc[4][4][4], uint32_t base,
                                         uint32_t wOff, int m0, int n0, int lane) {
    const int rowl = ((lane >> 3) & 1) * 8 + (lane & 7);
    const int k8   = (lane >> 4) & 1;
    const int l7   = lane & 7;
    uint32_t aBase[4], bBase[2];
#pragma unroll
    for (int s = 0; s < 4; s++)
        aBase[s] = base + S_P + (uint32_t)(m0 + s * 16 + rowl) * 256;
#pragma unroll
    for (int v = 0; v < 2; v++)
        bBase[v] = base + wOff + (uint32_t)(n0 + v * 16 + rowl) * 256;
#pragma unroll
    for (int ks = 0; ks < NKS; ks++) {
        const uint32_t swz = (uint32_t)(((ks * 2 + k8) ^ l7) << 4);
        uint32_t aH[4][4], bH[2][4];
#pragma unroll
        for (int s = 0; s < 4; s++) ldsm_x4(aH[s], aBase[s] + swz);
#pragma unroll
        for (int v = 0; v < 2; v++) ldsm_x4(bH[v], bBase[v] + swz);
#pragma unroll
        for (int v = 0; v < 2; v++)
#pragma unroll
            for (int h = 0; h < 2; h++) {
                const int u = v * 2 + h;
#pragma unroll
                for (int s = 0; s < 4; s++)
                    mma16816(acc[s][u], aH[s], bH[v][h], bH[v][h + 2]);
            }
    }
}

// bias+SiLU, round to f16, store in place into P; zero acc
__device__ __forceinline__ void epilogue(float acc[4][4][4], char* smem,
                                         const float* bias, int m0, int n0, int lane) {
    const int lr = lane >> 2, lc = (lane & 3) * 2;
#pragma unroll
    for (int s = 0; s < 4; s++)
#pragma unroll
        for (int u = 0; u < 4; u++) {
            int n_ = n0 + u * 8 + lc;
            float b0 = bias[n_], b1v = bias[n_ + 1];
            float v0 = silu_f(acc[s][u][0] + b0);
            float v1 = silu_f(acc[s][u][1] + b1v);
            float v2 = silu_f(acc[s][u][2] + b0);
            float v3 = silu_f(acc[s][u][3] + b1v);
            acc[s][u][0] = acc[s][u][1] = acc[s][u][2] = acc[s][u][3] = 0.0f;
            int mA = m0 + s * 16 + lr;
            int chunk = (n_ >> 3) ^ (lr & 7);
            uint32_t addrA = (uint32_t)mA * 256 + (chunk << 4) + lc * 2;
            *(uint32_t*)(smem + S_P + addrA) = pack2(v0, v1);
            int chunkB = (n_ >> 3) ^ ((lr + 8) & 7);
            uint32_t addrB = (uint32_t)(mA + 8) * 256 + (chunkB << 4) + lc * 2;
            *(uint32_t*)(smem + S_P + addrB) = pack2(v2, v3);
        }
}

// Fourier features chunk 0 (freqs 0..63, all real) into P; 256 threads
__device__ __forceinline__ void gen_feats0(char* smem, const float* sBx, const float* sBt,
                                           const float* sX, const float* sT, int tid) {
    const int m = tid >> 1, q = tid & 1;
    const float xv = sX[m], tv = sT[m];
    const int fbase = q * 32;
#pragma unroll
    for (int g = 0; g < 8; g++) {
        uint32_t hi4[4];
#pragma unroll
        for (int i = 0; i < 4; i++) {
            int f = fbase + g * 4 + i;
            float pr = TWO_PI_F * (xv * sBx[f] + tv * sBt[f]);
            float s, c;
            __sincosf(pr, &s, &c);
            hi4[i] = pack2(s, c);
        }
        int c0 = q * 64 + g * 8;
        uint32_t addr = (uint32_t)m * 256 + ((((c0 >> 3) ^ (m & 7)) << 4));
        *(uint4*)(smem + S_P + addr) = make_uint4(hi4[0], hi4[1], hi4[2], hi4[3]);
    }
}

// Fourier features chunk 1 (freqs 64..99 real, pad to 104; 80 cols) into P
__device__ __forceinline__ void gen_feats1(char* smem, const float* sBx, const float* sBt,
                                           const float* sX, const float* sT, int tid) {
    const int m = tid >> 1, q = tid & 1;
    const float xv = sX[m], tv = sT[m];
    const int fbase = 64 + q * 20;
#pragma unroll
    for (int g = 0; g < 5; g++) {
        uint32_t hi4[4];
#pragma unroll
        for (int i = 0; i < 4; i++) {
            int f = fbase + g * 4 + i;
            float s = 0.0f, c = 0.0f;
            if (f < FDIM) {
                float pr = TWO_PI_F * (xv * sBx[f] + tv * sBt[f]);
                __sincosf(pr, &s, &c);
            }
            hi4[i] = pack2(s, c);
        }
        int c0 = q * 40 + g * 8;
        uint32_t addr = (uint32_t)m * 256 + ((((c0 >> 3) ^ (m & 7)) << 4));
        *(uint4*)(smem + S_P + addr) = make_uint4(hi4[0], hi4[1], hi4[2], hi4[3]);
    }
}

__global__ void __launch_bounds__(NT, 2) xpinn_mma_kernel(
    const float* __restrict__ x, const float* __restrict__ t,
    const float* __restrict__ Bf,
    const float* __restrict__ b1, const float* __restrict__ b2,
    const float* __restrict__ b3,
    const float* __restrict__ W4, const float* __restrict__ b4,
    float* __restrict__ out) {
    const int dom = blockIdx.y;
    const int base_pt = blockIdx.x * TILE_M;
    const int cnt = g_counts[dom];
    if (base_pt >= cnt) return;

    extern __shared__ __align__(16) char smem[];
    const uint32_t sb = smem_u32(smem);
    const int tid = threadIdx.x;
    const int wid = tid >> 5, lane = tid & 31;
    const int m0 = (wid >> 2) * 64, n0 = (wid & 3) * 32, wn = wid & 3;
    const int nm = (cnt - base_pt < TILE_M) ? (cnt - base_pt) : TILE_M;

    float* sBx = (float*)(smem + S_MISC + MS_BX);
    float* sBt = (float*)(smem + S_MISC + MS_BT);
    float* sB1 = (float*)(smem + S_MISC + MS_B1);
    float* sB2 = (float*)(smem + S_MISC + MS_B2);
    float* sB3 = (float*)(smem + S_MISC + MS_B3);
    float* sW4 = (float*)(smem + S_MISC + MS_W4);
    float* sX  = (float*)(smem + S_MISC + MS_X);
    float* sT  = (float*)(smem + S_MISC + MS_T);
    int*   sIdx = (int*)(smem + S_MISC + MS_IDX);
    float* sPart = (float*)(smem + S_MISC + MS_PART);

    // Prefetch W1 both chunks into the two stages.
    cp_issue32k(sb + S_W0, g_w1_hi[dom][0], tid); CP_COMMIT();
    cp_issue32k(sb + S_W1, g_w1_hi[dom][1], tid); CP_COMMIT();

    if (tid < TILE_M) {
        if (tid < nm) {
            int i = g_idx[dom * N_MAX + base_pt + tid];
            sIdx[tid] = i; sX[tid] = x[i]; sT[tid] = t[i];
        } else { sIdx[tid] = -1; sX[tid] = 0.0f; sT[tid] = 0.0f; }
        sBx[tid] = (tid < FDIM) ? Bf[(dom * FDIM + tid) * 2]     : 0.0f;
        sBt[tid] = (tid < FDIM) ? Bf[(dom * FDIM + tid) * 2 + 1] : 0.0f;
        sB1[tid] = b1[dom * HDIM + tid];
        sB2[tid] = b2[dom * HDIM + tid];
        sB3[tid] = b3[dom * HDIM + tid];
        sW4[tid] = W4[dom * HDIM + tid];
    }
    __syncthreads();

    float acc[4][4][4];
#pragma unroll
    for (int s = 0; s < 4; s++)
#pragma unroll
        for (int u = 0; u < 4; u++)
#pragma unroll
            for (int r = 0; r < 4; r++) acc[s][u][r] = 0.0f;

    // ---- layer 1, K chunk 0 (W1c0 in stage0) ----
    gen_feats0(smem, sBx, sBt, sX, sT, tid);
    CP_WAIT(1);
    __syncthreads();
    mma_pass<8>(acc, sb, S_W0, m0, n0, lane);
    __syncthreads();
    // ---- layer 1, K chunk 1: 80 cols / 5 k-steps (feats in place; W2 -> stage0) ----
    gen_feats1(smem, sBx, sBt, sX, sT, tid);
    cp_issue32k(sb + S_W0, g_w2_hi[dom], tid); CP_COMMIT();
    CP_WAIT(1);
    __syncthreads();
    mma_pass<5>(acc, sb, S_W1, m0, n0, lane);
    __syncthreads();
    // ---- layer 2 (W2 in stage0; W3 -> stage1) ----
    epilogue(acc, smem, sB1, m0, n0, lane);
    cp_issue32k(sb + S_W1, g_w3_hi[dom], tid); CP_COMMIT();
    CP_WAIT(1);
    __syncthreads();
    mma_pass<8>(acc, sb, S_W0, m0, n0, lane);
    __syncthreads();
    // ---- layer 3 (W3 in stage1) ----
    epilogue(acc, smem, sB2, m0, n0, lane);
    CP_WAIT(0);
    __syncthreads();
    mma_pass<8>(acc, sb, S_W1, m0, n0, lane);
    __syncthreads();

    // ---- head: p = sum_n silu(z3 + b3[n]) * W4[n] ----
    {
        const int lr = lane >> 2, lc = (lane & 3) * 2;
        float hp[4][2];
#pragma unroll
        for (int s = 0; s < 4; s++) { hp[s][0] = 0.0f; hp[s][1] = 0.0f; }
#pragma unroll
        for (int s = 0; s < 4; s++)
#pragma unroll
            for (int u = 0; u < 4; u++) {
                int n_ = n0 + u * 8 + lc;
                float w0 = sW4[n_], w1 = sW4[n_ + 1];
                float b0 = sB3[n_], b1v = sB3[n_ + 1];
                hp[s][0] += silu_f(acc[s][u][0] + b0) * w0 + silu_f(acc[s][u][1] + b1v) * w1;
                hp[s][1] += silu_f(acc[s][u][2] + b0) * w0 + silu_f(acc[s][u][3] + b1v) * w1;
            }
#pragma unroll
        for (int off = 1; off <= 2; off <<= 1)
#pragma unroll
            for (int s = 0; s < 4; s++) {
                hp[s][0] += __shfl_xor_sync(0xFFFFFFFF, hp[s][0], off);
                hp[s][1] += __shfl_xor_sync(0xFFFFFFFF, hp[s][1], off);
            }
        if ((lane & 3) == 0)
#pragma unroll
            for (int s = 0; s < 4; s++) {
                sPart[wn * TILE_M + m0 + s * 16 + lr]     = hp[s][0];
                sPart[wn * TILE_M + m0 + s * 16 + lr + 8] = hp[s][1];
            }
    }
    __syncthreads();
    if (tid < nm)
        out[sIdx[tid]] = sPart[tid] + sPart[TILE_M + tid]
                       + sPart[2 * TILE_M + tid] + sPart[3 * TILE_M + tid] + b4[dom];
}

// ---------------- launch ----------------
extern "C" void kernel_launch(void* const* d_in, const int* in_sizes, int n_in,
                              void* d_out, int out_size) {
    const float* x  = (const float*)d_in[0];
    const float* t  = (const float*)d_in[1];
    const float* Bf = (const float*)d_in[2];
    const float* W1 = (const float*)d_in[3];
    const float* b1 = (const float*)d_in[4];
    const float* W2 = (const float*)d_in[5];
    const float* b2 = (const float*)d_in[6];
    const float* W3 = (const float*)d_in[7];
    const float* b3 = (const float*)d_in[8];
    const float* W4 = (const float*)d_in[9];
    const float* b4 = (const float*)d_in[10];
    float* out = (float*)d_out;
    const int n = in_sizes[0];
    (void)n_in; (void)out_size;

    cudaFuncSetAttribute(xpinn_mma_kernel,
                         cudaFuncAttributeMaxDynamicSharedMemorySize, SMEM_TOTAL);

    zero_counts_kernel<<<1, 32>>>();
    bucket_kernel<<<(n + 255) / 256, 256>>>(x, n);
    {
        const int total = DNUM * 2 * HDIM * HDIM + 2 * DNUM * HDIM * HDIM;
        prep_weights_kernel<<<(total + 255) / 256, 256>>>(W1, W2, W3);
    }
    dim3 grid((n + TILE_M - 1) / TILE_M, DNUM);
    xpinn_mma_kernel<<<grid, NT, SMEM_TOTAL>>>(x, t, Bf, b1, b2, b3, W4, b4, out);
}

// round 15
// speedup vs baseline: 2.0152x; 1.3740x over previous
#include <cuda_runtime.h>
#include <cuda_fp16.h>
#include <math.h>
#include <stdint.h>

#define DNUM   4
#define N_MAX  262144
#define FDIM   100
#define HDIM   128
#define TILE_M 128
#define NT     256
#define TWO_PI_F 6.2831853071795864769f

// ---------------- device scratch (allocation-free) ----------------
__device__ int g_counts[DNUM];
__device__ int g_idx[DNUM * N_MAX];
// f16 weights, transposed [n][k], XOR-swizzled images, 32KB each.
// W1 chunk1 uses only 80 k-cols (freqs 64..99 + pad to 104).
__device__ __align__(16) uint8_t g_w1_hi[DNUM][2][32768];
__device__ __align__(16) uint8_t g_w2_hi[DNUM][32768];
__device__ __align__(16) uint8_t g_w3_hi[DNUM][32768];

// swizzled byte offset inside a [rows][128 cols-f16] image (256B rows)
__device__ __host__ __forceinline__ int sw_off(int row, int col) {
    return row * 256 + ((((col >> 3) ^ (row & 7)) << 4)) + ((col & 7) << 1);
}

// ---------------- prep kernels ----------------
__global__ void zero_counts_kernel() {
    if (threadIdx.x < DNUM) g_counts[threadIdx.x] = 0;
}

// Block-aggregated bucketing: 4 smem counters, one global atomic per domain per block.
__global__ void bucket_kernel(const float* __restrict__ x, int n) {
    __shared__ int s_cnt[DNUM];
    __shared__ int s_base[DNUM];
    const int tid = threadIdx.x;
    if (tid < DNUM) s_cnt[tid] = 0;
    __syncthreads();
    const int i = blockIdx.x * blockDim.x + tid;
    int d = 0, pos = 0;
    if (i < n) {
        float xv = x[i];
        d = (xv < -0.5f) ? 0 : (xv < 0.0f) ? 1 : (xv < 0.5f) ? 2 : 3;
        pos = atomicAdd(&s_cnt[d], 1);
    }
    __syncthreads();
    if (tid < DNUM) s_base[tid] = atomicAdd(&g_counts[tid], s_cnt[tid]);
    __syncthreads();
    if (i < n) g_idx[d * N_MAX + s_base[d] + pos] = i;
}

// W1 col j: f=j>>1, s=j&1 -> W1 row f+100s (f>=100 pad 0).
__global__ void prep_weights_kernel(const float* __restrict__ W1,
                                    const float* __restrict__ W2,
                                    const float* __restrict__ W3) {
    const int T1 = DNUM * 2 * HDIM * HDIM;
    const int T2 = DNUM * HDIM * HDIM;
    int idx = blockIdx.x * blockDim.x + threadIdx.x;
    float w; uint8_t* hiA; int off;
    if (idx < T1) {
        int d = idx / (2 * HDIM * HDIM), r = idx % (2 * HDIM * HDIM);
        int c = r / (HDIM * HDIM), r2 = r % (HDIM * HDIM);
        int k = r2 / HDIM, n = r2 % HDIM;
        int j = c * 128 + k, f = j >> 1, s = j & 1;
        w = (f < FDIM) ? W1[((size_t)d * 2 * FDIM + (f + FDIM * s)) * HDIM + n] : 0.0f;
        off = sw_off(n, k); hiA = g_w1_hi[d][c];
    } else if (idx < T1 + T2) {
        int r0 = idx - T1;
        int d = r0 / (HDIM * HDIM), r2 = r0 % (HDIM * HDIM);
        int k = r2 / HDIM, n = r2 % HDIM;
        w = W2[((size_t)d * HDIM + k) * HDIM + n];
        off = sw_off(n, k); hiA = g_w2_hi[d];
    } else if (idx < T1 + 2 * T2) {
        int r0 = idx - T1 - T2;
        int d = r0 / (HDIM * HDIM), r2 = r0 % (HDIM * HDIM);
        int k = r2 / HDIM, n = r2 % HDIM;
        w = W3[((size_t)d * HDIM + k) * HDIM + n];
        off = sw_off(n, k); hiA = g_w3_hi[d];
    } else return;
    *(__half*)(hiA + off) = __float2half_rn(w);
}

// ---------------- asm helpers ----------------
__device__ __forceinline__ uint32_t smem_u32(const void* p) {
    uint32_t a;
    asm("{ .reg .u64 t; cvta.to.shared.u64 t, %1; cvt.u32.u64 %0, t; }" : "=r"(a) : "l"(p));
    return a;
}
__device__ __forceinline__ void ldsm_x4(uint32_t* r, uint32_t addr) {
    asm volatile("ldmatrix.sync.aligned.m8n8.x4.shared.b16 {%0,%1,%2,%3}, [%4];"
        : "=r"(r[0]), "=r"(r[1]), "=r"(r[2]), "=r"(r[3]) : "r"(addr));
}
__device__ __forceinline__ void mma16816(float* d, const uint32_t* a, uint32_t b0, uint32_t b1) {
    asm volatile("mma.sync.aligned.m16n8k16.row.col.f32.f16.f16.f32 "
        "{%0,%1,%2,%3}, {%4,%5,%6,%7}, {%8,%9}, {%0,%1,%2,%3};"
        : "+f"(d[0]), "+f"(d[1]), "+f"(d[2]), "+f"(d[3])
        : "r"(a[0]), "r"(a[1]), "r"(a[2]), "r"(a[3]), "r"(b0), "r"(b1));
}
#define CP_COMMIT() asm volatile("cp.async.commit_group;" ::: "memory")
#define CP_WAIT(n)  asm volatile("cp.async.wait_group %0;" :: "n"(n) : "memory")
__device__ __forceinline__ void cp_issue32k(uint32_t smem_dst, const uint8_t* gsrc, int tid) {
#pragma unroll
    for (int i = 0; i < 8; i++) {
        int off = (tid + i * NT) * 16;
        asm volatile("cp.async.cg.shared.global [%0], [%1], 16;"
            :: "r"(smem_dst + off), "l"(gsrc + off) : "memory");
    }
}

// ---------------- SMEM layout (bytes) ----------------
#define S_P      0          // activations, 128x128 f16 swizzled, 32KB
#define S_W0     32768      // weight stage 0, 32KB
#define S_W1     65536      // weight stage 1, 32KB
#define S_MISC   98304
#define MS_BX    0          // 128 f32
#define MS_BT    512
#define MS_B1    1024
#define MS_B2    1536
#define MS_B3    2048
#define MS_W4    2560
#define MS_X     3072
#define MS_T     3584
#define MS_IDX   4096
#define MS_PART  4608       // 4 x 128 f32
#define SMEM_TOTAL (S_MISC + 4608 + 2048)

// Fast SiLU: approximate reciprocal (MUFU.RCP + mul) instead of IEEE divide.
__device__ __forceinline__ float silu_f(float v) {
    return __fdividef(v, 1.0f + __expf(-v));
}
__device__ __forceinline__ uint32_t pack2(float a, float b) {
    __half2 h = __halves2half2(__float2half_rn(a), __float2half_rn(b));
    return *(uint32_t*)&h;
}

// One K=16*NKS MMA pass: acc += A(P) * W(stage).  Warp tile: 64(M) x 32(N).
template <int NKS>
__device__ __forceinline__ void mma_pass(float acc[4][4][4], uint32_t base,
                                         uint32_t wOff, int m0, int n0, int lane) {
    const int rowl = ((lane >> 3) & 1) * 8 + (lane & 7);
    const int k8   = (lane >> 4) & 1;
    const int l7   = lane & 7;
    uint32_t aBase[4], bBase[2];
#pragma unroll
    for (int s = 0; s < 4; s++)
        aBase[s] = base + S_P + (uint32_t)(m0 + s * 16 + rowl) * 256;
#pragma unroll
    for (int v = 0; v < 2; v++)
        bBase[v] = base + wOff + (uint32_t)(n0 + v * 16 + rowl) * 256;
#pragma unroll
    for (int ks = 0; ks < NKS; ks++) {
        const uint32_t swz = (uint32_t)(((ks * 2 + k8) ^ l7) << 4);
        uint32_t aH[4][4], bH[2][4];
#pragma unroll
        for (int s = 0; s < 4; s++) ldsm_x4(aH[s], aBase[s] + swz);
#pragma unroll
        for (int v = 0; v < 2; v++) ldsm_x4(bH[v], bBase[v] + swz);
#pragma unroll
        for (int v = 0; v < 2; v++)
#pragma unroll
            for (int h = 0; h < 2; h++) {
                const int u = v * 2 + h;
#pragma unroll
                for (int s = 0; s < 4; s++)
                    mma16816(acc[s][u], aH[s], bH[v][h], bH[v][h + 2]);
            }
    }
}

// bias+SiLU, round to f16, store in place into P; zero acc
__device__ __forceinline__ void epilogue(float acc[4][4][4], char* smem,
                                         const float* bias, int m0, int n0, int lane) {
    const int lr = lane >> 2, lc = (lane & 3) * 2;
#pragma unroll
    for (int s = 0; s < 4; s++)
#pragma unroll
        for (int u = 0; u < 4; u++) {
            int n_ = n0 + u * 8 + lc;
            float b0 = bias[n_], b1v = bias[n_ + 1];
            float v0 = silu_f(acc[s][u][0] + b0);
            float v1 = silu_f(acc[s][u][1] + b1v);
            float v2 = silu_f(acc[s][u][2] + b0);
            float v3 = silu_f(acc[s][u][3] + b1v);
            acc[s][u][0] = acc[s][u][1] = acc[s][u][2] = acc[s][u][3] = 0.0f;
            int mA = m0 + s * 16 + lr;
            int chunk = (n_ >> 3) ^ (lr & 7);
            uint32_t addrA = (uint32_t)mA * 256 + (chunk << 4) + lc * 2;
            *(uint32_t*)(smem + S_P + addrA) = pack2(v0, v1);
            int chunkB = (n_ >> 3) ^ ((lr + 8) & 7);
            uint32_t addrB = (uint32_t)(mA + 8) * 256 + (chunkB << 4) + lc * 2;
            *(uint32_t*)(smem + S_P + addrB) = pack2(v2, v3);
        }
}

// Fourier features chunk 0 (freqs 0..63, all real) into P; 256 threads
__device__ __forceinline__ void gen_feats0(char* smem, const float* sBx, const float* sBt,
                                           const float* sX, const float* sT, int tid) {
    const int m = tid >> 1, q = tid & 1;
    const float xv = sX[m], tv = sT[m];
    const int fbase = q * 32;
#pragma unroll
    for (int g = 0; g < 8; g++) {
        uint32_t hi4[4];
#pragma unroll
        for (int i = 0; i < 4; i++) {
            int f = fbase + g * 4 + i;
            float pr = TWO_PI_F * (xv * sBx[f] + tv * sBt[f]);
            float s, c;
            __sincosf(pr, &s, &c);
            hi4[i] = pack2(s, c);
        }
        int c0 = q * 64 + g * 8;
        uint32_t addr = (uint32_t)m * 256 + ((((c0 >> 3) ^ (m & 7)) << 4));
        *(uint4*)(smem + S_P + addr) = make_uint4(hi4[0], hi4[1], hi4[2], hi4[3]);
    }
}

// Fourier features chunk 1 (freqs 64..99 real, pad to 104; 80 cols) into P
__device__ __forceinline__ void gen_feats1(char* smem, const float* sBx, const float* sBt,
                                           const float* sX, const float* sT, int tid) {
    const int m = tid >> 1, q = tid & 1;
    const float xv = sX[m], tv = sT[m];
    const int fbase = 64 + q * 20;
#pragma unroll
    for (int g = 0; g < 5; g++) {
        uint32_t hi4[4];
#pragma unroll
        for (int i = 0; i < 4; i++) {
            int f = fbase + g * 4 + i;
            float s = 0.0f, c = 0.0f;
            if (f < FDIM) {
                float pr = TWO_PI_F * (xv * sBx[f] + tv * sBt[f]);
                __sincosf(pr, &s, &c);
            }
            hi4[i] = pack2(s, c);
        }
        int c0 = q * 40 + g * 8;
        uint32_t addr = (uint32_t)m * 256 + ((((c0 >> 3) ^ (m & 7)) << 4));
        *(uint4*)(smem + S_P + addr) = make_uint4(hi4[0], hi4[1], hi4[2], hi4[3]);
    }
}

__global__ void __launch_bounds__(NT, 2) xpinn_mma_kernel(
    const float* __restrict__ x, const float* __restrict__ t,
    const float* __restrict__ Bf,
    const float* __restrict__ b1, const float* __restrict__ b2,
    const float* __restrict__ b3,
    const float* __restrict__ W4, const float* __restrict__ b4,
    float* __restrict__ out) {
    const int dom = blockIdx.y;
    const int base_pt = blockIdx.x * TILE_M;
    const int cnt = g_counts[dom];
    if (base_pt >= cnt) return;

    extern __shared__ __align__(16) char smem[];
    const uint32_t sb = smem_u32(smem);
    const int tid = threadIdx.x;
    const int wid = tid >> 5, lane = tid & 31;
    const int m0 = (wid >> 2) * 64, n0 = (wid & 3) * 32, wn = wid & 3;
    const int nm = (cnt - base_pt < TILE_M) ? (cnt - base_pt) : TILE_M;

    float* sBx = (float*)(smem + S_MISC + MS_BX);
    float* sBt = (float*)(smem + S_MISC + MS_BT);
    float* sB1 = (float*)(smem + S_MISC + MS_B1);
    float* sB2 = (float*)(smem + S_MISC + MS_B2);
    float* sB3 = (float*)(smem + S_MISC + MS_B3);
    float* sW4 = (float*)(smem + S_MISC + MS_W4);
    float* sX  = (float*)(smem + S_MISC + MS_X);
    float* sT  = (float*)(smem + S_MISC + MS_T);
    int*   sIdx = (int*)(smem + S_MISC + MS_IDX);
    float* sPart = (float*)(smem + S_MISC + MS_PART);

    // Prefetch W1 both chunks into the two stages.
    cp_issue32k(sb + S_W0, g_w1_hi[dom][0], tid); CP_COMMIT();
    cp_issue32k(sb + S_W1, g_w1_hi[dom][1], tid); CP_COMMIT();

    if (tid < TILE_M) {
        if (tid < nm) {
            int i = g_idx[dom * N_MAX + base_pt + tid];
            sIdx[tid] = i; sX[tid] = x[i]; sT[tid] = t[i];
        } else { sIdx[tid] = -1; sX[tid] = 0.0f; sT[tid] = 0.0f; }
        sBx[tid] = (tid < FDIM) ? Bf[(dom * FDIM + tid) * 2]     : 0.0f;
        sBt[tid] = (tid < FDIM) ? Bf[(dom * FDIM + tid) * 2 + 1] : 0.0f;
        sB1[tid] = b1[dom * HDIM + tid];
        sB2[tid] = b2[dom * HDIM + tid];
        sB3[tid] = b3[dom * HDIM + tid];
        sW4[tid] = W4[dom * HDIM + tid];
    }
    __syncthreads();

    float acc[4][4][4];
#pragma unroll
    for (int s = 0; s < 4; s++)
#pragma unroll
        for (int u = 0; u < 4; u++)
#pragma unroll
            for (int r = 0; r < 4; r++) acc[s][u][r] = 0.0f;

    // ---- layer 1, K chunk 0 (W1c0 in stage0) ----
    gen_feats0(smem, sBx, sBt, sX, sT, tid);
    CP_WAIT(1);
    __syncthreads();
    mma_pass<8>(acc, sb, S_W0, m0, n0, lane);
    __syncthreads();
    // ---- layer 1, K chunk 1: 80 cols / 5 k-steps (feats in place; W2 -> stage0) ----
    gen_feats1(smem, sBx, sBt, sX, sT, tid);
    cp_issue32k(sb + S_W0, g_w2_hi[dom], tid); CP_COMMIT();
    CP_WAIT(1);
    __syncthreads();
    mma_pass<5>(acc, sb, S_W1, m0, n0, lane);
    __syncthreads();
    // ---- layer 2 (W2 in stage0; W3 -> stage1) ----
    epilogue(acc, smem, sB1, m0, n0, lane);
    cp_issue32k(sb + S_W1, g_w3_hi[dom], tid); CP_COMMIT();
    CP_WAIT(1);
    __syncthreads();
    mma_pass<8>(acc, sb, S_W0, m0, n0, lane);
    __syncthreads();
    // ---- layer 3 (W3 in stage1) ----
    epilogue(acc, smem, sB2, m0, n0, lane);
    CP_WAIT(0);
    __syncthreads();
    mma_pass<8>(acc, sb, S_W1, m0, n0, lane);
    // (no sync needed: head uses only registers + stable smem)

    // ---- head: p = sum_n silu(z3 + b3[n]) * W4[n] ----
    {
        const int lr = lane >> 2, lc = (lane & 3) * 2;
        float hp[4][2];
#pragma unroll
        for (int s = 0; s < 4; s++) { hp[s][0] = 0.0f; hp[s][1] = 0.0f; }
#pragma unroll
        for (int s = 0; s < 4; s++)
#pragma unroll
            for (int u = 0; u < 4; u++) {
                int n_ = n0 + u * 8 + lc;
                float w0 = sW4[n_], w1 = sW4[n_ + 1];
                float b0 = sB3[n_], b1v = sB3[n_ + 1];
                hp[s][0] += silu_f(acc[s][u][0] + b0) * w0 + silu_f(acc[s][u][1] + b1v) * w1;
                hp[s][1] += silu_f(acc[s][u][2] + b0) * w0 + silu_f(acc[s][u][3] + b1v) * w1;
            }
#pragma unroll
        for (int off = 1; off <= 2; off <<= 1)
#pragma unroll
            for (int s = 0; s < 4; s++) {
                hp[s][0] += __shfl_xor_sync(0xFFFFFFFF, hp[s][0], off);
                hp[s][1] += __shfl_xor_sync(0xFFFFFFFF, hp[s][1], off);
            }
        if ((lane & 3) == 0)
#pragma unroll
            for (int s = 0; s < 4; s++) {
                sPart[wn * TILE_M + m0 + s * 16 + lr]     = hp[s][0];
                sPart[wn * TILE_M + m0 + s * 16 + lr + 8] = hp[s][1];
            }
    }
    __syncthreads();
    if (tid < nm)
        out[sIdx[tid]] = sPart[tid] + sPart[TILE_M + tid]
                       + sPart[2 * TILE_M + tid] + sPart[3 * TILE_M + tid] + b4[dom];
}

// ---------------- launch ----------------
extern "C" void kernel_launch(void* const* d_in, const int* in_sizes, int n_in,
                              void* d_out, int out_size) {
    const float* x  = (const float*)d_in[0];
    const float* t  = (const float*)d_in[1];
    const float* Bf = (const float*)d_in[2];
    const float* W1 = (const float*)d_in[3];
    const float* b1 = (const float*)d_in[4];
    const float* W2 = (const float*)d_in[5];
    const float* b2 = (const float*)d_in[6];
    const float* W3 = (const float*)d_in[7];
    const float* b3 = (const float*)d_in[8];
    const float* W4 = (const float*)d_in[9];
    const float* b4 = (const float*)d_in[10];
    float* out = (float*)d_out;
    const int n = in_sizes[0];
    (void)n_in; (void)out_size;

    cudaFuncSetAttribute(xpinn_mma_kernel,
                         cudaFuncAttributeMaxDynamicSharedMemorySize, SMEM_TOTAL);

    zero_counts_kernel<<<1, 32>>>();
    bucket_kernel<<<(n + 255) / 256, 256>>>(x, n);
    {
        const int total = DNUM * 2 * HDIM * HDIM + 2 * DNUM * HDIM * HDIM;
        prep_weights_kernel<<<(total + 255) / 256, 256>>>(W1, W2, W3);
    }
    dim3 grid((n + TILE_M - 1) / TILE_M, DNUM);
    xpinn_mma_kernel<<<grid, NT, SMEM_TOTAL>>>(x, t, Bf, b1, b2, b3, W4, b4, out);
}

// round 16
// speedup vs baseline: 2.1722x; 1.0779x over previous
#include <cuda_runtime.h>
#include <cuda_fp16.h>
#include <math.h>
#include <stdint.h>

#define DNUM   4
#define N_MAX  262144
#define FDIM   100
#define HDIM   128
#define TILE_M 128
#define NT     256
#define TWO_PI_F 6.2831853071795864769f

// ---------------- device scratch (allocation-free) ----------------
__device__ int g_counts[DNUM];
__device__ int g_idx[DNUM * N_MAX];
// f16 weights, transposed [n][k], XOR-swizzled images, 32KB each.
// W1 chunk1 uses only 80 k-cols (freqs 64..99 + pad to 104).
__device__ __align__(16) uint8_t g_w1_hi[DNUM][2][32768];
__device__ __align__(16) uint8_t g_w2_hi[DNUM][32768];
__device__ __align__(16) uint8_t g_w3_hi[DNUM][32768];

// swizzled byte offset inside a [rows][128 cols-f16] image (256B rows)
__device__ __host__ __forceinline__ int sw_off(int row, int col) {
    return row * 256 + ((((col >> 3) ^ (row & 7)) << 4)) + ((col & 7) << 1);
}

// ---------------- prep kernels ----------------
__global__ void zero_counts_kernel() {
    if (threadIdx.x < DNUM) g_counts[threadIdx.x] = 0;
}

// Block-aggregated bucketing: 4 smem counters, one global atomic per domain per block.
__global__ void bucket_kernel(const float* __restrict__ x, int n) {
    __shared__ int s_cnt[DNUM];
    __shared__ int s_base[DNUM];
    const int tid = threadIdx.x;
    if (tid < DNUM) s_cnt[tid] = 0;
    __syncthreads();
    const int i = blockIdx.x * blockDim.x + tid;
    int d = 0, pos = 0;
    if (i < n) {
        float xv = x[i];
        d = (xv < -0.5f) ? 0 : (xv < 0.0f) ? 1 : (xv < 0.5f) ? 2 : 3;
        pos = atomicAdd(&s_cnt[d], 1);
    }
    __syncthreads();
    if (tid < DNUM) s_base[tid] = atomicAdd(&g_counts[tid], s_cnt[tid]);
    __syncthreads();
    if (i < n) g_idx[d * N_MAX + s_base[d] + pos] = i;
}

// W1 col j: f=j>>1, s=j&1 -> W1 row f+100s (f>=100 pad 0).
__global__ void prep_weights_kernel(const float* __restrict__ W1,
                                    const float* __restrict__ W2,
                                    const float* __restrict__ W3) {
    const int T1 = DNUM * 2 * HDIM * HDIM;
    const int T2 = DNUM * HDIM * HDIM;
    int idx = blockIdx.x * blockDim.x + threadIdx.x;
    float w; uint8_t* hiA; int off;
    if (idx < T1) {
        int d = idx / (2 * HDIM * HDIM), r = idx % (2 * HDIM * HDIM);
        int c = r / (HDIM * HDIM), r2 = r % (HDIM * HDIM);
        int k = r2 / HDIM, n = r2 % HDIM;
        int j = c * 128 + k, f = j >> 1, s = j & 1;
        w = (f < FDIM) ? W1[((size_t)d * 2 * FDIM + (f + FDIM * s)) * HDIM + n] : 0.0f;
        off = sw_off(n, k); hiA = g_w1_hi[d][c];
    } else if (idx < T1 + T2) {
        int r0 = idx - T1;
        int d = r0 / (HDIM * HDIM), r2 = r0 % (HDIM * HDIM);
        int k = r2 / HDIM, n = r2 % HDIM;
        w = W2[((size_t)d * HDIM + k) * HDIM + n];
        off = sw_off(n, k); hiA = g_w2_hi[d];
    } else if (idx < T1 + 2 * T2) {
        int r0 = idx - T1 - T2;
        int d = r0 / (HDIM * HDIM), r2 = r0 % (HDIM * HDIM);
        int k = r2 / HDIM, n = r2 % HDIM;
        w = W3[((size_t)d * HDIM + k) * HDIM + n];
        off = sw_off(n, k); hiA = g_w3_hi[d];
    } else return;
    *(__half*)(hiA + off) = __float2half_rn(w);
}

// ---------------- asm helpers ----------------
__device__ __forceinline__ uint32_t smem_u32(const void* p) {
    uint32_t a;
    asm("{ .reg .u64 t; cvta.to.shared.u64 t, %1; cvt.u32.u64 %0, t; }" : "=r"(a) : "l"(p));
    return a;
}
__device__ __forceinline__ void ldsm_x4(uint32_t* r, uint32_t addr) {
    asm volatile("ldmatrix.sync.aligned.m8n8.x4.shared.b16 {%0,%1,%2,%3}, [%4];"
        : "=r"(r[0]), "=r"(r[1]), "=r"(r[2]), "=r"(r[3]) : "r"(addr));
}
__device__ __forceinline__ void mma16816(float* d, const uint32_t* a, uint32_t b0, uint32_t b1) {
    asm volatile("mma.sync.aligned.m16n8k16.row.col.f32.f16.f16.f32 "
        "{%0,%1,%2,%3}, {%4,%5,%6,%7}, {%8,%9}, {%0,%1,%2,%3};"
        : "+f"(d[0]), "+f"(d[1]), "+f"(d[2]), "+f"(d[3])
        : "r"(a[0]), "r"(a[1]), "r"(a[2]), "r"(a[3]), "r"(b0), "r"(b1));
}
#define CP_COMMIT() asm volatile("cp.async.commit_group;" ::: "memory")
#define CP_WAIT(n)  asm volatile("cp.async.wait_group %0;" :: "n"(n) : "memory")
__device__ __forceinline__ void cp_issue32k(uint32_t smem_dst, const uint8_t* gsrc, int tid) {
#pragma unroll
    for (int i = 0; i < 8; i++) {
        int off = (tid + i * NT) * 16;
        asm volatile("cp.async.cg.shared.global [%0], [%1], 16;"
            :: "r"(smem_dst + off), "l"(gsrc + off) : "memory");
    }
}

// ---------------- SMEM layout (bytes) ----------------
#define S_P      0          // activations, 128x128 f16 swizzled, 32KB
#define S_W0     32768      // weight stage 0, 32KB
#define S_W1     65536      // weight stage 1, 32KB
#define S_MISC   98304
#define MS_BX    0          // 128 f32
#define MS_BT    512
#define MS_B1    1024
#define MS_B2    1536
#define MS_B3    2048
#define MS_W4    2560
#define MS_X     3072
#define MS_T     3584
#define MS_IDX   4096
#define MS_PART  4608       // 4 x 128 f32
#define SMEM_TOTAL (S_MISC + 4608 + 2048)

// Fast SiLU via single-MUFU tanh: v*sigmoid(v) = v*(0.5 + 0.5*tanh(v/2)).
__device__ __forceinline__ float silu_f(float v) {
    float th;
    asm("tanh.approx.f32 %0, %1;" : "=f"(th) : "f"(0.5f * v));
    return v * fmaf(0.5f, th, 0.5f);
}
// Single-instruction f32x2 -> f16x2 pack (a in low half, b in high half).
__device__ __forceinline__ uint32_t pack2(float a, float b) {
    uint32_t r;
    asm("cvt.rn.f16x2.f32 %0, %1, %2;" : "=r"(r) : "f"(b), "f"(a));
    return r;
}

// One K=16*NKS MMA pass: acc += A(P) * W(stage).  Warp tile: 64(M) x 32(N).
template <int NKS>
__device__ __forceinline__ void mma_pass(float acc[4][4][4], uint32_t base,
                                         uint32_t wOff, int m0, int n0, int lane) {
    const int rowl = ((lane >> 3) & 1) * 8 + (lane & 7);
    const int k8   = (lane >> 4) & 1;
    const int l7   = lane & 7;
    uint32_t aBase[4], bBase[2];
#pragma unroll
    for (int s = 0; s < 4; s++)
        aBase[s] = base + S_P + (uint32_t)(m0 + s * 16 + rowl) * 256;
#pragma unroll
    for (int v = 0; v < 2; v++)
        bBase[v] = base + wOff + (uint32_t)(n0 + v * 16 + rowl) * 256;
#pragma unroll
    for (int ks = 0; ks < NKS; ks++) {
        const uint32_t swz = (uint32_t)(((ks * 2 + k8) ^ l7) << 4);
        uint32_t aH[4][4], bH[2][4];
#pragma unroll
        for (int s = 0; s < 4; s++) ldsm_x4(aH[s], aBase[s] + swz);
#pragma unroll
        for (int v = 0; v < 2; v++) ldsm_x4(bH[v], bBase[v] + swz);
#pragma unroll
        for (int v = 0; v < 2; v++)
#pragma unroll
            for (int h = 0; h < 2; h++) {
                const int u = v * 2 + h;
#pragma unroll
                for (int s = 0; s < 4; s++)
                    mma16816(acc[s][u], aH[s], bH[v][h], bH[v][h + 2]);
            }
    }
}

// bias+SiLU, round to f16, store in place into P; zero acc
__device__ __forceinline__ void epilogue(float acc[4][4][4], char* smem,
                                         const float* bias, int m0, int n0, int lane) {
    const int lr = lane >> 2, lc = (lane & 3) * 2;
#pragma unroll
    for (int s = 0; s < 4; s++)
#pragma unroll
        for (int u = 0; u < 4; u++) {
            int n_ = n0 + u * 8 + lc;
            float b0 = bias[n_], b1v = bias[n_ + 1];
            float v0 = silu_f(acc[s][u][0] + b0);
            float v1 = silu_f(acc[s][u][1] + b1v);
            float v2 = silu_f(acc[s][u][2] + b0);
            float v3 = silu_f(acc[s][u][3] + b1v);
            acc[s][u][0] = acc[s][u][1] = acc[s][u][2] = acc[s][u][3] = 0.0f;
            int mA = m0 + s * 16 + lr;
            int chunk = (n_ >> 3) ^ (lr & 7);
            uint32_t addrA = (uint32_t)mA * 256 + (chunk << 4) + lc * 2;
            *(uint32_t*)(smem + S_P + addrA) = pack2(v0, v1);
            int chunkB = (n_ >> 3) ^ ((lr + 8) & 7);
            uint32_t addrB = (uint32_t)(mA + 8) * 256 + (chunkB << 4) + lc * 2;
            *(uint32_t*)(smem + S_P + addrB) = pack2(v2, v3);
        }
}

// Fourier features chunk 0 (freqs 0..63, all real) into P; 256 threads.
// sBx/sBt are pre-scaled by 2*pi.
__device__ __forceinline__ void gen_feats0(char* smem, const float* sBx, const float* sBt,
                                           const float* sX, const float* sT, int tid) {
    const int m = tid >> 1, q = tid & 1;
    const float xv = sX[m], tv = sT[m];
    const int fbase = q * 32;
#pragma unroll
    for (int g = 0; g < 8; g++) {
        uint32_t hi4[4];
#pragma unroll
        for (int i = 0; i < 4; i++) {
            int f = fbase + g * 4 + i;
            float pr = xv * sBx[f] + tv * sBt[f];
            float s, c;
            __sincosf(pr, &s, &c);
            hi4[i] = pack2(s, c);
        }
        int c0 = q * 64 + g * 8;
        uint32_t addr = (uint32_t)m * 256 + ((((c0 >> 3) ^ (m & 7)) << 4));
        *(uint4*)(smem + S_P + addr) = make_uint4(hi4[0], hi4[1], hi4[2], hi4[3]);
    }
}

// Fourier features chunk 1 (freqs 64..99 real, pad to 104; 80 cols) into P
__device__ __forceinline__ void gen_feats1(char* smem, const float* sBx, const float* sBt,
                                           const float* sX, const float* sT, int tid) {
    const int m = tid >> 1, q = tid & 1;
    const float xv = sX[m], tv = sT[m];
    const int fbase = 64 + q * 20;
#pragma unroll
    for (int g = 0; g < 5; g++) {
        uint32_t hi4[4];
#pragma unroll
        for (int i = 0; i < 4; i++) {
            int f = fbase + g * 4 + i;
            float s = 0.0f, c = 0.0f;
            if (f < FDIM) {
                float pr = xv * sBx[f] + tv * sBt[f];
                __sincosf(pr, &s, &c);
            }
            hi4[i] = pack2(s, c);
        }
        int c0 = q * 40 + g * 8;
        uint32_t addr = (uint32_t)m * 256 + ((((c0 >> 3) ^ (m & 7)) << 4));
        *(uint4*)(smem + S_P + addr) = make_uint4(hi4[0], hi4[1], hi4[2], hi4[3]);
    }
}

__global__ void __launch_bounds__(NT, 2) xpinn_mma_kernel(
    const float* __restrict__ x, const float* __restrict__ t,
    const float* __restrict__ Bf,
    const float* __restrict__ b1, const float* __restrict__ b2,
    const float* __restrict__ b3,
    const float* __restrict__ W4, const float* __restrict__ b4,
    float* __restrict__ out) {
    const int dom = blockIdx.y;
    const int base_pt = blockIdx.x * TILE_M;
    const int cnt = g_counts[dom];
    if (base_pt >= cnt) return;

    extern __shared__ __align__(16) char smem[];
    const uint32_t sb = smem_u32(smem);
    const int tid = threadIdx.x;
    const int wid = tid >> 5, lane = tid & 31;
    const int m0 = (wid >> 2) * 64, n0 = (wid & 3) * 32, wn = wid & 3;
    const int nm = (cnt - base_pt < TILE_M) ? (cnt - base_pt) : TILE_M;

    float* sBx = (float*)(smem + S_MISC + MS_BX);
    float* sBt = (float*)(smem + S_MISC + MS_BT);
    float* sB1 = (float*)(smem + S_MISC + MS_B1);
    float* sB2 = (float*)(smem + S_MISC + MS_B2);
    float* sB3 = (float*)(smem + S_MISC + MS_B3);
    float* sW4 = (float*)(smem + S_MISC + MS_W4);
    float* sX  = (float*)(smem + S_MISC + MS_X);
    float* sT  = (float*)(smem + S_MISC + MS_T);
    int*   sIdx = (int*)(smem + S_MISC + MS_IDX);
    float* sPart = (float*)(smem + S_MISC + MS_PART);

    // Prefetch W1 both chunks into the two stages.
    cp_issue32k(sb + S_W0, g_w1_hi[dom][0], tid); CP_COMMIT();
    cp_issue32k(sb + S_W1, g_w1_hi[dom][1], tid); CP_COMMIT();

    if (tid < TILE_M) {
        if (tid < nm) {
            int i = g_idx[dom * N_MAX + base_pt + tid];
            sIdx[tid] = i; sX[tid] = x[i]; sT[tid] = t[i];
        } else { sIdx[tid] = -1; sX[tid] = 0.0f; sT[tid] = 0.0f; }
        sBx[tid] = (tid < FDIM) ? TWO_PI_F * Bf[(dom * FDIM + tid) * 2]     : 0.0f;
        sBt[tid] = (tid < FDIM) ? TWO_PI_F * Bf[(dom * FDIM + tid) * 2 + 1] : 0.0f;
        sB1[tid] = b1[dom * HDIM + tid];
        sB2[tid] = b2[dom * HDIM + tid];
        sB3[tid] = b3[dom * HDIM + tid];
        sW4[tid] = W4[dom * HDIM + tid];
    }
    __syncthreads();

    float acc[4][4][4];
#pragma unroll
    for (int s = 0; s < 4; s++)
#pragma unroll
        for (int u = 0; u < 4; u++)
#pragma unroll
            for (int r = 0; r < 4; r++) acc[s][u][r] = 0.0f;

    // ---- layer 1, K chunk 0 (W1c0 in stage0) ----
    gen_feats0(smem, sBx, sBt, sX, sT, tid);
    CP_WAIT(1);
    __syncthreads();
    mma_pass<8>(acc, sb, S_W0, m0, n0, lane);
    __syncthreads();
    // ---- layer 1, K chunk 1: 80 cols / 5 k-steps (feats in place; W2 -> stage0) ----
    gen_feats1(smem, sBx, sBt, sX, sT, tid);
    cp_issue32k(sb + S_W0, g_w2_hi[dom], tid); CP_COMMIT();
    CP_WAIT(1);
    __syncthreads();
    mma_pass<5>(acc, sb, S_W1, m0, n0, lane);
    __syncthreads();
    // ---- layer 2 (W2 in stage0; W3 -> stage1) ----
    epilogue(acc, smem, sB1, m0, n0, lane);
    cp_issue32k(sb + S_W1, g_w3_hi[dom], tid); CP_COMMIT();
    CP_WAIT(1);
    __syncthreads();
    mma_pass<8>(acc, sb, S_W0, m0, n0, lane);
    __syncthreads();
    // ---- layer 3 (W3 in stage1) ----
    epilogue(acc, smem, sB2, m0, n0, lane);
    CP_WAIT(0);
    __syncthreads();
    mma_pass<8>(acc, sb, S_W1, m0, n0, lane);
    // (no sync needed: head uses only registers + stable smem)

    // ---- head: p = sum_n silu(z3 + b3[n]) * W4[n] ----
    {
        const int lr = lane >> 2, lc = (lane & 3) * 2;
        float hp[4][2];
#pragma unroll
        for (int s = 0; s < 4; s++) { hp[s][0] = 0.0f; hp[s][1] = 0.0f; }
#pragma unroll
        for (int s = 0; s < 4; s++)
#pragma unroll
            for (int u = 0; u < 4; u++) {
                int n_ = n0 + u * 8 + lc;
                float w0 = sW4[n_], w1 = sW4[n_ + 1];
                float b0 = sB3[n_], b1v = sB3[n_ + 1];
                hp[s][0] += silu_f(acc[s][u][0] + b0) * w0 + silu_f(acc[s][u][1] + b1v) * w1;
                hp[s][1] += silu_f(acc[s][u][2] + b0) * w0 + silu_f(acc[s][u][3] + b1v) * w1;
            }
#pragma unroll
        for (int off = 1; off <= 2; off <<= 1)
#pragma unroll
            for (int s = 0; s < 4; s++) {
                hp[s][0] += __shfl_xor_sync(0xFFFFFFFF, hp[s][0], off);
                hp[s][1] += __shfl_xor_sync(0xFFFFFFFF, hp[s][1], off);
            }
        if ((lane & 3) == 0)
#pragma unroll
            for (int s = 0; s < 4; s++) {
                sPart[wn * TILE_M + m0 + s * 16 + lr]     = hp[s][0];
                sPart[wn * TILE_M + m0 + s * 16 + lr + 8] = hp[s][1];
            }
    }
    __syncthreads();
    if (tid < nm)
        out[sIdx[tid]] = sPart[tid] + sPart[TILE_M + tid]
                       + sPart[2 * TILE_M + tid] + sPart[3 * TILE_M + tid] + b4[dom];
}

// ---------------- launch ----------------
extern "C" void kernel_launch(void* const* d_in, const int* in_sizes, int n_in,
                              void* d_out, int out_size) {
    const float* x  = (const float*)d_in[0];
    const float* t  = (const float*)d_in[1];
    const float* Bf = (const float*)d_in[2];
    const float* W1 = (const float*)d_in[3];
    const float* b1 = (const float*)d_in[4];
    const float* W2 = (const float*)d_in[5];
    const float* b2 = (const float*)d_in[6];
    const float* W3 = (const float*)d_in[7];
    const float* b3 = (const float*)d_in[8];
    const float* W4 = (const float*)d_in[9];
    const float* b4 = (const float*)d_in[10];
    float* out = (float*)d_out;
    const int n = in_sizes[0];
    (void)n_in; (void)out_size;

    cudaFuncSetAttribute(xpinn_mma_kernel,
                         cudaFuncAttributeMaxDynamicSharedMemorySize, SMEM_TOTAL);

    zero_counts_kernel<<<1, 32>>>();
    bucket_kernel<<<(n + 255) / 256, 256>>>(x, n);
    {
        const int total = DNUM * 2 * HDIM * HDIM + 2 * DNUM * HDIM * HDIM;
        prep_weights_kernel<<<(total + 255) / 256, 256>>>(W1, W2, W3);
    }
    dim3 grid((n + TILE_M - 1) / TILE_M, DNUM);
    xpinn_mma_kernel<<<grid, NT, SMEM_TOTAL>>>(x, t, Bf, b1, b2, b3, W4, b4, out);
}